// round 7
// baseline (speedup 1.0000x reference)
#include <cuda_runtime.h>
#include <cuda_bf16.h>
#include <math.h>
#include <stdint.h>

// ---------------- problem constants ----------------
#define T_FR   8
#define N_TOK  257
#define HW     16
#define BATCH  8
#define D_MOD  768
#define DH     192
#define HEADS  4
#define HDIM   48
#define M_ALL  (T_FR * BATCH * N_TOK)   // 16448
#define M_PAT  (BATCH * T_FR * HW * HW) // 16384
#define KCUBE  27

// ---------------- scratch ----------------
__device__ float g_t1 [M_ALL * DH];       // fc1 out fp32 (residual for conv)
__device__ float g_xs [M_ALL * DH];       // gelu out fp32 (LN input, proj residual source)
__device__ float g_qkv[M_PAT * 3 * DH];   // qkv fp32 (attention input)

__device__ __nv_bfloat16 g_xb  [M_ALL * D_MOD];
__device__ __nv_bfloat16 g_t1b [M_ALL * DH];
__device__ __nv_bfloat16 g_xsb [M_ALL * DH];
__device__ __nv_bfloat16 g_yb  [M_PAT * DH];
__device__ __nv_bfloat16 g_attb[M_PAT * DH];

__device__ __nv_bfloat16 g_w_fc1 [DH * D_MOD];
__device__ __nv_bfloat16 g_w_conv[DH * DH];    // Mc = convB_w @ convA_w
__device__ float         g_b_conv[DH];         // cB@convA_b + convB_b
__device__ __nv_bfloat16 g_w_qkv [3 * DH * DH];
__device__ __nv_bfloat16 g_w_proj[DH * DH];
__device__ __nv_bfloat16 g_w_fc2 [D_MOD * DH];

// ---------------- helpers ----------------
__device__ __forceinline__ float gelu_exact(float v) {
    return 0.5f * v * (1.0f + erff(v * 0.70710678118654752f));
}

__device__ __forceinline__ int patch_to_xs_row(int pr) {
    int b = pr >> 11;
    int t = (pr >> 8) & 7;
    int h = (pr >> 4) & 15;
    int w = pr & 15;
    return t * (BATCH * N_TOK) + b * N_TOK + 1 + (h << 4) + w;
}

__device__ __forceinline__ uint32_t pack_bf2(float lo, float hi) {
    uint32_t r;
    asm("cvt.rn.bf16x2.f32 %0, %1, %2;" : "=r"(r) : "f"(hi), "f"(lo));
    return r;
}

__device__ __forceinline__ uint32_t smem_u32(const void* p) {
    uint32_t a;
    asm("{ .reg .u64 t; cvta.to.shared.u64 t, %1; cvt.u32.u64 %0, t; }"
        : "=r"(a) : "l"(p));
    return a;
}

#define CP16(dst, src) \
    asm volatile("cp.async.cg.shared.global [%0], [%1], 16;" \
        :: "r"(dst), "l"(src) : "memory")
#define CP_COMMIT() asm volatile("cp.async.commit_group;" ::: "memory")
#define CP_WAIT(N)  asm volatile("cp.async.wait_group %0;" :: "n"(N) : "memory")

#define LDSM4(r0, r1, r2, r3, addr) \
    asm volatile("ldmatrix.sync.aligned.m8n8.x4.shared.b16 {%0,%1,%2,%3}, [%4];" \
        : "=r"(r0), "=r"(r1), "=r"(r2), "=r"(r3) : "r"(addr))

#define MMA16816(cc, A0, A1, A2, A3, B0, B1) \
    asm volatile("mma.sync.aligned.m16n8k16.row.col.f32.bf16.bf16.f32 " \
        "{%0,%1,%2,%3}, {%4,%5,%6,%7}, {%8,%9}, {%0,%1,%2,%3};" \
        : "+f"((cc)[0]), "+f"((cc)[1]), "+f"((cc)[2]), "+f"((cc)[3]) \
        : "r"(A0), "r"(A1), "r"(A2), "r"(A3), "r"(B0), "r"(B1))

// ---------------- bf16 GEMM: 3-stage cp.async + ldmatrix + mma.sync ----------------
// C = A(MxK,bf16) @ W(NxK,bf16)^T + bias. BM=128, BN=64, BK=32. 256 thr, 8 warps 4x2.
// MODE 0: v ; 1: gelu(res[m]+v) ; 2: res[rr]+v stored at rr ; 3: res[m]+v
#define ASTRIDE 80            // bytes per smem row (40 bf16) -> conflict-free
#define A_ST (128 * ASTRIDE)  // 10240
#define B_ST (64 * ASTRIDE)   // 5120
#define STAGE (A_ST + B_ST)   // 15360
#define NSTG 3                // 46080 B static smem (< 48K limit)

template <int MODE, bool WF32, bool WBF16>
__global__ __launch_bounds__(256)
void tc_gemm(const __nv_bfloat16* __restrict__ A,
             const __nv_bfloat16* __restrict__ W,
             const float* __restrict__ bias,
             float* __restrict__ Cf,
             __nv_bfloat16* __restrict__ Cb,
             int M, int N, int Kc,
             const float* __restrict__ res)
{
    __shared__ __align__(128) uint8_t smem[NSTG * STAGE];

    const int tid    = threadIdx.x;
    const int warpid = tid >> 5;
    const int lane   = tid & 31;
    const int m0     = blockIdx.y * 128;
    const int n0     = blockIdx.x * 64;

    const int wm = (warpid >> 1) * 32;
    const int wn = (warpid & 1) * 32;

    const uint32_t sbase = smem_u32(smem);

    // cp.async mapping
    const int r4 = tid >> 2;          // 0..63
    const int c4 = tid & 3;
    const int rowA0 = min(m0 + r4, M - 1);
    const int rowA1 = min(m0 + 64 + r4, M - 1);
    const __nv_bfloat16* Ap0 = A + (size_t)rowA0 * Kc + c4 * 8;
    const __nv_bfloat16* Ap1 = A + (size_t)rowA1 * Kc + c4 * 8;
    const __nv_bfloat16* Bp  = W + (size_t)(n0 + r4) * Kc + c4 * 8;
    const uint32_t dA0 = (uint32_t)(r4 * ASTRIDE + c4 * 16);
    const uint32_t dA1 = (uint32_t)((64 + r4) * ASTRIDE + c4 * 16);
    const uint32_t dB  = (uint32_t)(A_ST + r4 * ASTRIDE + c4 * 16);

    // ldmatrix lane addressing
    const int l8  = lane & 7;
    const int mtx = lane >> 3;
    const uint32_t aoff = (uint32_t)((wm + (mtx & 1) * 8 + l8) * ASTRIDE + (mtx >> 1) * 16);
    const uint32_t boff = (uint32_t)(A_ST + (wn + (mtx >> 1) * 8 + l8) * ASTRIDE + (mtx & 1) * 16);

    float acc[2][4][4];
    #pragma unroll
    for (int i = 0; i < 2; i++)
        #pragma unroll
        for (int j = 0; j < 4; j++)
            #pragma unroll
            for (int q = 0; q < 4; q++) acc[i][j][q] = 0.f;

    const int KT = Kc / 32;

    // prologue: stage 0,1
    #pragma unroll
    for (int s = 0; s < 2; s++) {
        if (s < KT) {
            uint32_t b = sbase + s * STAGE;
            const int ko = s * 32;
            CP16(b + dA0, Ap0 + ko);
            CP16(b + dA1, Ap1 + ko);
            CP16(b + dB,  Bp  + ko);
            CP_COMMIT();
        }
    }

    int buf = 0;
    for (int kt = 0; kt < KT; kt++) {
        if (kt + 1 < KT) { CP_WAIT(1); } else { CP_WAIT(0); }
        __syncthreads();

        // issue kt+2 into the buffer freed at iteration kt-1
        if (kt + 2 < KT) {
            int nb = buf + 2; if (nb >= NSTG) nb -= NSTG;
            uint32_t b = sbase + nb * STAGE;
            const int ko = (kt + 2) * 32;
            CP16(b + dA0, Ap0 + ko);
            CP16(b + dA1, Ap1 + ko);
            CP16(b + dB,  Bp  + ko);
            CP_COMMIT();
        }

        const uint32_t abase = sbase + buf * STAGE + aoff;
        const uint32_t bbase = sbase + buf * STAGE + boff;

        #pragma unroll
        for (int ks = 0; ks < 2; ks++) {
            uint32_t a0[4], a1[4], b0[4], b1[4];
            LDSM4(a0[0], a0[1], a0[2], a0[3], abase + ks * 32);
            LDSM4(a1[0], a1[1], a1[2], a1[3], abase + 16 * ASTRIDE + ks * 32);
            LDSM4(b0[0], b0[1], b0[2], b0[3], bbase + ks * 32);
            LDSM4(b1[0], b1[1], b1[2], b1[3], bbase + 16 * ASTRIDE + ks * 32);

            MMA16816(acc[0][0], a0[0], a0[1], a0[2], a0[3], b0[0], b0[1]);
            MMA16816(acc[0][1], a0[0], a0[1], a0[2], a0[3], b0[2], b0[3]);
            MMA16816(acc[0][2], a0[0], a0[1], a0[2], a0[3], b1[0], b1[1]);
            MMA16816(acc[0][3], a0[0], a0[1], a0[2], a0[3], b1[2], b1[3]);
            MMA16816(acc[1][0], a1[0], a1[1], a1[2], a1[3], b0[0], b0[1]);
            MMA16816(acc[1][1], a1[0], a1[1], a1[2], a1[3], b0[2], b0[3]);
            MMA16816(acc[1][2], a1[0], a1[1], a1[2], a1[3], b1[0], b1[1]);
            MMA16816(acc[1][3], a1[0], a1[1], a1[2], a1[3], b1[2], b1[3]);
        }

        if (++buf == NSTG) buf = 0;
    }

    // epilogue
    const int r  = lane >> 2;
    const int c2 = (lane & 3) * 2;

    #pragma unroll
    for (int mi = 0; mi < 2; mi++) {
        #pragma unroll
        for (int half = 0; half < 2; half++) {
            const int m = m0 + wm + mi * 16 + r + half * 8;
            if (m >= M) continue;
            const int orow = (MODE == 2) ? patch_to_xs_row(m) : m;
            #pragma unroll
            for (int nj = 0; nj < 4; nj++) {
                const int n = n0 + wn + nj * 8 + c2;
                float v0 = acc[mi][nj][half * 2 + 0] + bias[n];
                float v1 = acc[mi][nj][half * 2 + 1] + bias[n + 1];
                if (MODE == 1) {
                    const float2 rv = *(const float2*)(res + (size_t)m * N + n);
                    v0 = gelu_exact(rv.x + v0);
                    v1 = gelu_exact(rv.y + v1);
                } else if (MODE == 2) {
                    const float2 rv = *(const float2*)(res + (size_t)orow * N + n);
                    v0 += rv.x; v1 += rv.y;
                } else if (MODE == 3) {
                    const float2 rv = *(const float2*)(res + (size_t)m * N + n);
                    v0 += rv.x; v1 += rv.y;
                }
                if (WF32) {
                    float2 o; o.x = v0; o.y = v1;
                    *(float2*)(Cf + (size_t)orow * N + n) = o;
                }
                if (WBF16) {
                    *(uint32_t*)(Cb + (size_t)orow * N + n) = pack_bf2(v0, v1);
                }
            }
        }
    }
}

// ---------------- fp32 -> bf16 conversion ----------------
__global__ void f2b_kernel(const float* __restrict__ s,
                           __nv_bfloat16* __restrict__ d, int n)
{
    int i = (blockIdx.x * blockDim.x + threadIdx.x) * 4;
    if (i + 3 < n) {
        float4 v = *(const float4*)(s + i);
        uint2 o;
        o.x = pack_bf2(v.x, v.y);
        o.y = pack_bf2(v.z, v.w);
        *(uint2*)((uint16_t*)d + i) = o;
    } else {
        for (; i < n; i++) d[i] = __float2bfloat16(s[i]);
    }
}

__global__ void wconv_kernel(const float* s0, const float* s3,
                             const float* s4, const float* s5)
{
    const int stride = gridDim.x * blockDim.x;
    const int t = blockIdx.x * blockDim.x + threadIdx.x;
    for (int i = t; i < DH * D_MOD;   i += stride) g_w_fc1[i]  = __float2bfloat16(s0[i]);
    for (int i = t; i < 3 * DH * DH;  i += stride) g_w_qkv[i]  = __float2bfloat16(s3[i]);
    for (int i = t; i < DH * DH;      i += stride) g_w_proj[i] = __float2bfloat16(s4[i]);
    for (int i = t; i < D_MOD * DH;   i += stride) g_w_fc2[i]  = __float2bfloat16(s5[i]);
}

// Mc = convB_w(192x64) @ convA_w(64x192); b' = convB_w @ convA_b + convB_b
__global__ void mconv_kernel(const float* __restrict__ cA, const float* __restrict__ cAb,
                             const float* __restrict__ cB, const float* __restrict__ cBb)
{
    const int idx = blockIdx.x * blockDim.x + threadIdx.x;
    if (idx < DH * DH) {
        const int i = idx / DH, j = idx % DH;
        float s = 0.f;
        #pragma unroll 8
        for (int k = 0; k < 64; k++)
            s = fmaf(cB[i * 64 + k], cA[k * DH + j], s);
        g_w_conv[idx] = __float2bfloat16(s);
    } else if (idx < DH * DH + DH) {
        const int i = idx - DH * DH;
        float s = cBb[i];
        for (int k = 0; k < 64; k++)
            s = fmaf(cB[i * 64 + k], cAb[k], s);
        g_b_conv[i] = s;
    }
}

// ---------------- LayerNorm (fp32 in, bf16 out) ----------------
__global__ void ln_kernel(const float* __restrict__ xs,
                          const float* __restrict__ gamma,
                          const float* __restrict__ beta,
                          __nv_bfloat16* __restrict__ y)
{
    const int pr  = blockIdx.x;
    const int tid = threadIdx.x;
    const int row = patch_to_xs_row(pr);

    float v = xs[(size_t)row * DH + tid];

    __shared__ float red[40];

    float s = v;
    #pragma unroll
    for (int off = 16; off > 0; off >>= 1) s += __shfl_down_sync(0xffffffff, s, off);
    if ((tid & 31) == 0) red[tid >> 5] = s;
    __syncthreads();
    if (tid == 0) {
        float tot = 0.f;
        #pragma unroll
        for (int i = 0; i < 6; i++) tot += red[i];
        red[32] = tot * (1.0f / DH);
    }
    __syncthreads();
    float mu = red[32];

    float d  = v - mu;
    float s2 = d * d;
    #pragma unroll
    for (int off = 16; off > 0; off >>= 1) s2 += __shfl_down_sync(0xffffffff, s2, off);
    if ((tid & 31) == 0) red[8 + (tid >> 5)] = s2;
    __syncthreads();
    if (tid == 0) {
        float tot = 0.f;
        #pragma unroll
        for (int i = 0; i < 6; i++) tot += red[8 + i];
        red[33] = rsqrtf(tot * (1.0f / DH) + 1e-5f);
    }
    __syncthreads();

    y[(size_t)pr * DH + tid] = __float2bfloat16(d * red[33] * gamma[tid] + beta[tid]);
}

// ---------------- 3D neighborhood attention (fp32 in, bf16 out) ----------------
#define KROW 193

__global__ void attn_kernel(const float* __restrict__ qkv,
                            const float* __restrict__ rpb,
                            __nv_bfloat16* __restrict__ att)
{
    const int pr  = blockIdx.x;
    const int tid = threadIdx.x;
    const int b = pr >> 11;
    const int t = (pr >> 8) & 7;
    const int h = (pr >> 4) & 15;
    const int w = pr & 15;

    __shared__ float s_k[KCUBE * KROW];
    __shared__ float s_q[DH];
    __shared__ int   s_nbr[KCUBE];
    __shared__ float s_sc[HEADS * KCUBE];
    __shared__ float s_p [HEADS * KCUBE];

    const float scale = 0.144337567297406f;   // 48^-0.5
    s_q[tid] = qkv[(size_t)pr * (3 * DH) + tid] * scale;

    const int st = min(max(t - 1, 0), T_FR - 3);
    const int sh = min(max(h - 1, 0), HW - 3);
    const int sw = min(max(w - 1, 0), HW - 3);

    if (tid < KCUBE) {
        int kt = tid / 9, kh = (tid / 3) % 3, kw = tid % 3;
        s_nbr[tid] = (((b * T_FR + st + kt) * HW) + sh + kh) * HW + sw + kw;
    }
    __syncthreads();

    #pragma unroll 4
    for (int nb = 0; nb < KCUBE; nb++)
        s_k[nb * KROW + tid] = qkv[(size_t)s_nbr[nb] * (3 * DH) + DH + tid];
    __syncthreads();

    if (tid < HEADS * KCUBE) {
        int head = tid / KCUBE, nb = tid % KCUBE;
        const float* kp = s_k + nb * KROW + head * HDIM;
        const float* qp = s_q + head * HDIM;
        float s = 0.f;
        #pragma unroll
        for (int j = 0; j < HDIM; j++) s = fmaf(qp[j], kp[j], s);
        int kt = nb / 9, kh = (nb / 3) % 3, kw = nb % 3;
        int rt = st + kt - t + 2;
        int rh = sh + kh - h + 2;
        int rw = sw + kw - w + 2;
        s += rpb[((head * 5 + rt) * 5 + rh) * 5 + rw];
        s_sc[tid] = s;
    }
    __syncthreads();

    if (tid < HEADS) {
        float mx = -1e30f;
        #pragma unroll
        for (int i = 0; i < KCUBE; i++) mx = fmaxf(mx, s_sc[tid * KCUBE + i]);
        float sum = 0.f;
        #pragma unroll
        for (int i = 0; i < KCUBE; i++) {
            float e = __expf(s_sc[tid * KCUBE + i] - mx);
            s_p[tid * KCUBE + i] = e;
            sum += e;
        }
        float inv = 1.0f / sum;
        #pragma unroll
        for (int i = 0; i < KCUBE; i++) s_p[tid * KCUBE + i] *= inv;
    }
    __syncthreads();

    {
        int head = tid / HDIM;
        float o = 0.f;
        #pragma unroll
        for (int nb = 0; nb < KCUBE; nb++)
            o = fmaf(s_p[head * KCUBE + nb],
                     qkv[(size_t)s_nbr[nb] * (3 * DH) + 2 * DH + tid], o);
        att[(size_t)pr * DH + tid] = __float2bfloat16(o);
    }
}

// ---------------- launch ----------------
extern "C" void kernel_launch(void* const* d_in, const int* in_sizes, int n_in,
                              void* d_out, int out_size)
{
    const float* x       = (const float*)d_in[0];
    const float* fc1_w   = (const float*)d_in[1];
    const float* fc1_b   = (const float*)d_in[2];
    const float* convA_w = (const float*)d_in[3];
    const float* convA_b = (const float*)d_in[4];
    const float* convB_w = (const float*)d_in[5];
    const float* convB_b = (const float*)d_in[6];
    const float* ln_g    = (const float*)d_in[7];
    const float* ln_b    = (const float*)d_in[8];
    const float* qkv_w   = (const float*)d_in[9];
    const float* qkv_b   = (const float*)d_in[10];
    const float* rpb     = (const float*)d_in[11];
    const float* proj_w  = (const float*)d_in[12];
    const float* proj_b  = (const float*)d_in[13];
    const float* fc2_w   = (const float*)d_in[14];
    const float* fc2_b   = (const float*)d_in[15];
    float* out = (float*)d_out;

    float *t1, *xs, *qkv, *bconv;
    __nv_bfloat16 *xb, *t1b, *xsb, *yb, *attb;
    __nv_bfloat16 *wfc1, *wconv, *wqkv, *wproj, *wfc2;
    cudaGetSymbolAddress((void**)&t1,  g_t1);
    cudaGetSymbolAddress((void**)&xs,  g_xs);
    cudaGetSymbolAddress((void**)&qkv, g_qkv);
    cudaGetSymbolAddress((void**)&bconv, g_b_conv);
    cudaGetSymbolAddress((void**)&xb,   g_xb);
    cudaGetSymbolAddress((void**)&t1b,  g_t1b);
    cudaGetSymbolAddress((void**)&xsb,  g_xsb);
    cudaGetSymbolAddress((void**)&yb,   g_yb);
    cudaGetSymbolAddress((void**)&attb, g_attb);
    cudaGetSymbolAddress((void**)&wfc1,  g_w_fc1);
    cudaGetSymbolAddress((void**)&wconv, g_w_conv);
    cudaGetSymbolAddress((void**)&wqkv,  g_w_qkv);
    cudaGetSymbolAddress((void**)&wproj, g_w_proj);
    cudaGetSymbolAddress((void**)&wfc2,  g_w_fc2);

    const int gyA = (M_ALL + 127) / 128;   // 129
    const int gyP = M_PAT / 128;           // 128

    // 0) conversions + conv-weight fold
    {
        const int n = M_ALL * D_MOD;
        f2b_kernel<<<(n / 4 + 255) / 256, 256>>>(x, xb, n);
        wconv_kernel<<<114, 256>>>(fc1_w, qkv_w, proj_w, fc2_w);
        mconv_kernel<<<(DH * DH + DH + 255) / 256, 256>>>(convA_w, convA_b,
                                                          convB_w, convB_b);
    }
    // 1) fc1 -> t1 (f32) + t1b (bf16)
    tc_gemm<0, true, true><<<dim3(3, gyA), 256>>>(xb, wfc1, fc1_b, t1, t1b,
                                                  M_ALL, DH, D_MOD, nullptr);
    // 2) fused conv: gelu(t1 + t1b@Mc^T + b') -> xs (f32) + xsb (bf16)
    tc_gemm<1, true, true><<<dim3(3, gyA), 256>>>(t1b, wconv, bconv, xs, xsb,
                                                  M_ALL, DH, DH, t1);
    // 3) LayerNorm -> yb (bf16)
    ln_kernel<<<M_PAT, DH>>>(xs, ln_g, ln_b, yb);
    // 4) qkv -> qkv (f32)
    tc_gemm<0, true, false><<<dim3(9, gyP), 256>>>(yb, wqkv, qkv_b, qkv, nullptr,
                                                   M_PAT, 3 * DH, DH, nullptr);
    // 5) attention -> attb (bf16)
    attn_kernel<<<M_PAT, DH>>>(qkv, rpb, attb);
    // 6) proj: xsb[rr] = xs[rr] + proj(attb) + b   (bf16 out only)
    tc_gemm<2, false, true><<<dim3(3, gyP), 256>>>(attb, wproj, proj_b, nullptr, xsb,
                                                   M_PAT, DH, DH, xs);
    // 7) fc2 + outer residual(x) -> out (f32)
    tc_gemm<3, true, false><<<dim3(12, gyA), 256>>>(xsb, wfc2, fc2_b, out, nullptr,
                                                    M_ALL, D_MOD, DH, x);
}

// round 8
// speedup vs baseline: 1.2542x; 1.2542x over previous
#include <cuda_runtime.h>
#include <cuda_bf16.h>
#include <math.h>
#include <stdint.h>

// ---------------- problem constants ----------------
#define T_FR   8
#define N_TOK  257
#define HW     16
#define BATCH  8
#define D_MOD  768
#define DH     192
#define HEADS  4
#define HDIM   48
#define M_ALL  (T_FR * BATCH * N_TOK)   // 16448
#define M_PAT  (BATCH * T_FR * HW * HW) // 16384
#define KCUBE  27

// ---------------- scratch ----------------
__device__ float g_t1 [M_ALL * DH];       // fc1 out fp32 (residual for conv)
__device__ float g_xs [M_ALL * DH];       // gelu out fp32 (LN input, proj residual source)

__device__ __nv_bfloat16 g_xb  [M_ALL * D_MOD];
__device__ __nv_bfloat16 g_t1b [M_ALL * DH];
__device__ __nv_bfloat16 g_xsb [M_ALL * DH];
__device__ __nv_bfloat16 g_yb  [M_PAT * DH];
__device__ __nv_bfloat16 g_qkvb[M_PAT * 3 * DH];
__device__ __nv_bfloat16 g_attb[M_PAT * DH];

__device__ __nv_bfloat16 g_w_fc1 [DH * D_MOD];
__device__ __nv_bfloat16 g_w_conv[DH * DH];    // Mc = convB_w @ convA_w
__device__ float         g_b_conv[DH];         // cB@convA_b + convB_b
__device__ __nv_bfloat16 g_w_qkv [3 * DH * DH];
__device__ __nv_bfloat16 g_w_proj[DH * DH];
__device__ __nv_bfloat16 g_w_fc2 [D_MOD * DH];

// ---------------- helpers ----------------
__device__ __forceinline__ float gelu_exact(float v) {
    return 0.5f * v * (1.0f + erff(v * 0.70710678118654752f));
}

__device__ __forceinline__ int patch_to_xs_row(int pr) {
    int b = pr >> 11;
    int t = (pr >> 8) & 7;
    int h = (pr >> 4) & 15;
    int w = pr & 15;
    return t * (BATCH * N_TOK) + b * N_TOK + 1 + (h << 4) + w;
}

__device__ __forceinline__ uint32_t pack_bf2(float lo, float hi) {
    uint32_t r;
    asm("cvt.rn.bf16x2.f32 %0, %1, %2;" : "=r"(r) : "f"(hi), "f"(lo));
    return r;
}

__device__ __forceinline__ uint32_t smem_u32(const void* p) {
    uint32_t a;
    asm("{ .reg .u64 t; cvta.to.shared.u64 t, %1; cvt.u32.u64 %0, t; }"
        : "=r"(a) : "l"(p));
    return a;
}

#define CP16(dst, src) \
    asm volatile("cp.async.cg.shared.global [%0], [%1], 16;" \
        :: "r"(dst), "l"(src) : "memory")
#define CP_COMMIT() asm volatile("cp.async.commit_group;" ::: "memory")
#define CP_WAIT(N)  asm volatile("cp.async.wait_group %0;" :: "n"(N) : "memory")

#define LDSM4(r0, r1, r2, r3, addr) \
    asm volatile("ldmatrix.sync.aligned.m8n8.x4.shared.b16 {%0,%1,%2,%3}, [%4];" \
        : "=r"(r0), "=r"(r1), "=r"(r2), "=r"(r3) : "r"(addr))

#define MMA16816(cc, A0, A1, A2, A3, B0, B1) \
    asm volatile("mma.sync.aligned.m16n8k16.row.col.f32.bf16.bf16.f32 " \
        "{%0,%1,%2,%3}, {%4,%5,%6,%7}, {%8,%9}, {%0,%1,%2,%3};" \
        : "+f"((cc)[0]), "+f"((cc)[1]), "+f"((cc)[2]), "+f"((cc)[3]) \
        : "r"(A0), "r"(A1), "r"(A2), "r"(A3), "r"(B0), "r"(B1))

// ---------------- bf16 GEMM: 3-stage cp.async + ldmatrix + mma.sync ----------------
#define ASTRIDE 80
#define A_ST (128 * ASTRIDE)
#define B_ST (64 * ASTRIDE)
#define STAGE (A_ST + B_ST)
#define NSTG 3

template <int MODE, bool WF32, bool WBF16>
__global__ __launch_bounds__(256)
void tc_gemm(const __nv_bfloat16* __restrict__ A,
             const __nv_bfloat16* __restrict__ W,
             const float* __restrict__ bias,
             float* __restrict__ Cf,
             __nv_bfloat16* __restrict__ Cb,
             int M, int N, int Kc,
             const float* __restrict__ res)
{
    __shared__ __align__(128) uint8_t smem[NSTG * STAGE];

    const int tid    = threadIdx.x;
    const int warpid = tid >> 5;
    const int lane   = tid & 31;
    const int m0     = blockIdx.y * 128;
    const int n0     = blockIdx.x * 64;

    const int wm = (warpid >> 1) * 32;
    const int wn = (warpid & 1) * 32;

    const uint32_t sbase = smem_u32(smem);

    const int r4 = tid >> 2;
    const int c4 = tid & 3;
    const int rowA0 = min(m0 + r4, M - 1);
    const int rowA1 = min(m0 + 64 + r4, M - 1);
    const __nv_bfloat16* Ap0 = A + (size_t)rowA0 * Kc + c4 * 8;
    const __nv_bfloat16* Ap1 = A + (size_t)rowA1 * Kc + c4 * 8;
    const __nv_bfloat16* Bp  = W + (size_t)(n0 + r4) * Kc + c4 * 8;
    const uint32_t dA0 = (uint32_t)(r4 * ASTRIDE + c4 * 16);
    const uint32_t dA1 = (uint32_t)((64 + r4) * ASTRIDE + c4 * 16);
    const uint32_t dB  = (uint32_t)(A_ST + r4 * ASTRIDE + c4 * 16);

    const int l8  = lane & 7;
    const int mtx = lane >> 3;
    const uint32_t aoff = (uint32_t)((wm + (mtx & 1) * 8 + l8) * ASTRIDE + (mtx >> 1) * 16);
    const uint32_t boff = (uint32_t)(A_ST + (wn + (mtx >> 1) * 8 + l8) * ASTRIDE + (mtx & 1) * 16);

    float acc[2][4][4];
    #pragma unroll
    for (int i = 0; i < 2; i++)
        #pragma unroll
        for (int j = 0; j < 4; j++)
            #pragma unroll
            for (int q = 0; q < 4; q++) acc[i][j][q] = 0.f;

    const int KT = Kc / 32;

    #pragma unroll
    for (int s = 0; s < 2; s++) {
        if (s < KT) {
            uint32_t b = sbase + s * STAGE;
            const int ko = s * 32;
            CP16(b + dA0, Ap0 + ko);
            CP16(b + dA1, Ap1 + ko);
            CP16(b + dB,  Bp  + ko);
            CP_COMMIT();
        }
    }

    int buf = 0;
    for (int kt = 0; kt < KT; kt++) {
        if (kt + 1 < KT) { CP_WAIT(1); } else { CP_WAIT(0); }
        __syncthreads();

        if (kt + 2 < KT) {
            int nb = buf + 2; if (nb >= NSTG) nb -= NSTG;
            uint32_t b = sbase + nb * STAGE;
            const int ko = (kt + 2) * 32;
            CP16(b + dA0, Ap0 + ko);
            CP16(b + dA1, Ap1 + ko);
            CP16(b + dB,  Bp  + ko);
            CP_COMMIT();
        }

        const uint32_t abase = sbase + buf * STAGE + aoff;
        const uint32_t bbase = sbase + buf * STAGE + boff;

        #pragma unroll
        for (int ks = 0; ks < 2; ks++) {
            uint32_t a0[4], a1[4], b0[4], b1[4];
            LDSM4(a0[0], a0[1], a0[2], a0[3], abase + ks * 32);
            LDSM4(a1[0], a1[1], a1[2], a1[3], abase + 16 * ASTRIDE + ks * 32);
            LDSM4(b0[0], b0[1], b0[2], b0[3], bbase + ks * 32);
            LDSM4(b1[0], b1[1], b1[2], b1[3], bbase + 16 * ASTRIDE + ks * 32);

            MMA16816(acc[0][0], a0[0], a0[1], a0[2], a0[3], b0[0], b0[1]);
            MMA16816(acc[0][1], a0[0], a0[1], a0[2], a0[3], b0[2], b0[3]);
            MMA16816(acc[0][2], a0[0], a0[1], a0[2], a0[3], b1[0], b1[1]);
            MMA16816(acc[0][3], a0[0], a0[1], a0[2], a0[3], b1[2], b1[3]);
            MMA16816(acc[1][0], a1[0], a1[1], a1[2], a1[3], b0[0], b0[1]);
            MMA16816(acc[1][1], a1[0], a1[1], a1[2], a1[3], b0[2], b0[3]);
            MMA16816(acc[1][2], a1[0], a1[1], a1[2], a1[3], b1[0], b1[1]);
            MMA16816(acc[1][3], a1[0], a1[1], a1[2], a1[3], b1[2], b1[3]);
        }

        if (++buf == NSTG) buf = 0;
    }

    const int r  = lane >> 2;
    const int c2 = (lane & 3) * 2;

    #pragma unroll
    for (int mi = 0; mi < 2; mi++) {
        #pragma unroll
        for (int half = 0; half < 2; half++) {
            const int m = m0 + wm + mi * 16 + r + half * 8;
            if (m >= M) continue;
            const int orow = (MODE == 2) ? patch_to_xs_row(m) : m;
            #pragma unroll
            for (int nj = 0; nj < 4; nj++) {
                const int n = n0 + wn + nj * 8 + c2;
                float v0 = acc[mi][nj][half * 2 + 0] + bias[n];
                float v1 = acc[mi][nj][half * 2 + 1] + bias[n + 1];
                if (MODE == 1) {
                    const float2 rv = *(const float2*)(res + (size_t)m * N + n);
                    v0 = gelu_exact(rv.x + v0);
                    v1 = gelu_exact(rv.y + v1);
                } else if (MODE == 2) {
                    const float2 rv = *(const float2*)(res + (size_t)orow * N + n);
                    v0 += rv.x; v1 += rv.y;
                } else if (MODE == 3) {
                    const float2 rv = *(const float2*)(res + (size_t)m * N + n);
                    v0 += rv.x; v1 += rv.y;
                }
                if (WF32) {
                    float2 o; o.x = v0; o.y = v1;
                    *(float2*)(Cf + (size_t)orow * N + n) = o;
                }
                if (WBF16) {
                    *(uint32_t*)(Cb + (size_t)orow * N + n) = pack_bf2(v0, v1);
                }
            }
        }
    }
}

// ---------------- fp32 -> bf16 conversion ----------------
__global__ void f2b_kernel(const float* __restrict__ s,
                           __nv_bfloat16* __restrict__ d, int n)
{
    int i = (blockIdx.x * blockDim.x + threadIdx.x) * 4;
    if (i + 3 < n) {
        float4 v = *(const float4*)(s + i);
        uint2 o;
        o.x = pack_bf2(v.x, v.y);
        o.y = pack_bf2(v.z, v.w);
        *(uint2*)((uint16_t*)d + i) = o;
    } else {
        for (; i < n; i++) d[i] = __float2bfloat16(s[i]);
    }
}

__global__ void wconv_kernel(const float* s0, const float* s3,
                             const float* s4, const float* s5)
{
    const int stride = gridDim.x * blockDim.x;
    const int t = blockIdx.x * blockDim.x + threadIdx.x;
    for (int i = t; i < DH * D_MOD;   i += stride) g_w_fc1[i]  = __float2bfloat16(s0[i]);
    for (int i = t; i < 3 * DH * DH;  i += stride) g_w_qkv[i]  = __float2bfloat16(s3[i]);
    for (int i = t; i < DH * DH;      i += stride) g_w_proj[i] = __float2bfloat16(s4[i]);
    for (int i = t; i < D_MOD * DH;   i += stride) g_w_fc2[i]  = __float2bfloat16(s5[i]);
}

__global__ void mconv_kernel(const float* __restrict__ cA, const float* __restrict__ cAb,
                             const float* __restrict__ cB, const float* __restrict__ cBb)
{
    const int idx = blockIdx.x * blockDim.x + threadIdx.x;
    if (idx < DH * DH) {
        const int i = idx / DH, j = idx % DH;
        float s = 0.f;
        #pragma unroll 8
        for (int k = 0; k < 64; k++)
            s = fmaf(cB[i * 64 + k], cA[k * DH + j], s);
        g_w_conv[idx] = __float2bfloat16(s);
    } else if (idx < DH * DH + DH) {
        const int i = idx - DH * DH;
        float s = cBb[i];
        for (int k = 0; k < 64; k++)
            s = fmaf(cB[i * 64 + k], cAb[k], s);
        g_b_conv[i] = s;
    }
}

// ---------------- LayerNorm: warp-per-row ----------------
__global__ __launch_bounds__(256)
void ln_warp(const float* __restrict__ xs,
             const float* __restrict__ gamma,
             const float* __restrict__ beta,
             __nv_bfloat16* __restrict__ y)
{
    const int wid  = threadIdx.x >> 5;
    const int lane = threadIdx.x & 31;
    const int pr   = blockIdx.x * 8 + wid;     // grid = 2048
    const int row  = patch_to_xs_row(pr);

    const float* src = xs + (size_t)row * DH;
    float v[6];
    float s = 0.f;
    #pragma unroll
    for (int k = 0; k < 6; k++) { v[k] = src[lane + 32 * k]; s += v[k]; }
    #pragma unroll
    for (int o = 16; o > 0; o >>= 1) s += __shfl_xor_sync(0xffffffff, s, o);
    const float mu = s * (1.0f / DH);

    float s2 = 0.f;
    #pragma unroll
    for (int k = 0; k < 6; k++) { v[k] -= mu; s2 += v[k] * v[k]; }
    #pragma unroll
    for (int o = 16; o > 0; o >>= 1) s2 += __shfl_xor_sync(0xffffffff, s2, o);
    const float inv = rsqrtf(s2 * (1.0f / DH) + 1e-5f);

    #pragma unroll
    for (int k = 0; k < 6; k++) {
        const int c = lane + 32 * k;
        y[(size_t)pr * DH + c] = __float2bfloat16(v[k] * inv * gamma[c] + beta[c]);
    }
}

// ---------------- tiled 3D neighborhood attention ----------------
// One block = 4x4 spatial tile of 16 tokens (same b,t). K/V union <= 3*6*6=108 rows
// staged once in smem (bf16). 256 threads.
#define KSTR 200   // bf16 units per smem row (192 + pad), 400B: 16B-aligned
#define RMAX 108
#define OFF_K 0
#define OFF_V (RMAX * KSTR * 2)                 // 43200
#define OFF_Q (OFF_V + RMAX * KSTR * 2)         // 86400
#define OFF_P (OFF_Q + 16 * DH * 4)             // 98688
#define OFF_R (OFF_P + 16 * 108 * 4)            // 105600
#define SMEM_ATT (OFF_R + 16 * 27 * 4)          // 107328

__global__ __launch_bounds__(256)
void attn_tiled(const __nv_bfloat16* __restrict__ qkvb,
                const float* __restrict__ rpb,
                __nv_bfloat16* __restrict__ att)
{
    extern __shared__ __align__(16) uint8_t dyn[];
    __nv_bfloat16* s_k = (__nv_bfloat16*)(dyn + OFF_K);
    __nv_bfloat16* s_v = (__nv_bfloat16*)(dyn + OFF_V);
    float*         s_q = (float*)(dyn + OFF_Q);
    float*         s_p = (float*)(dyn + OFF_P);
    int*           s_r = (int*)(dyn + OFF_R);

    const int tid  = threadIdx.x;
    const int wid  = tid >> 5;
    const int lane = tid & 31;

    int bid = blockIdx.x;
    const int tw = bid & 3;  bid >>= 2;
    const int th = bid & 3;  bid >>= 2;
    const int t  = bid & 7;  bid >>= 3;
    const int b  = bid;
    const int h0 = th * 4, w0 = tw * 4;

    const int st  = min(max(t - 1, 0), T_FR - 3);
    const int hU0 = max(h0 - 1, 0), hU1 = min(h0 + 4, 15);
    const int wU0 = max(w0 - 1, 0), wU1 = min(w0 + 4, 15);
    const int nH  = hU1 - hU0 + 1;
    const int nW  = wU1 - wU0 + 1;
    const int R   = 3 * nH * nW;

    // ---- stage K+V union rows (contiguous 768B = 48 uint4 per row) ----
    for (int r = wid; r < R; r += 8) {
        const int f   = r / (nH * nW);
        const int rem = r - f * (nH * nW);
        const int hh  = hU0 + rem / nW;
        const int ww  = wU0 + rem % nW;
        const int grow = ((b * T_FR + st + f) * HW + hh) * HW + ww;
        const uint4* src = (const uint4*)(qkvb + (size_t)grow * (3 * DH) + DH);
        uint4* dk = (uint4*)(s_k + r * KSTR);
        uint4* dv = (uint4*)(s_v + r * KSTR);
        {
            const int ch = lane;
            if (ch < 24) dk[ch] = src[ch];
            else         dv[ch - 24] = src[ch];
        }
        if (lane < 16) {
            const int ch = lane + 32;
            dv[ch - 24] = src[ch];
        }
    }

    // ---- stage q (scaled fp32) ----
    const float scale = 0.144337567297406f;   // 48^-0.5
    for (int idx = tid; idx < 16 * DH; idx += 256) {
        const int i = idx / DH, c = idx - i * DH;
        const int hh = h0 + (i >> 2), ww = w0 + (i & 3);
        const int grow = ((b * T_FR + t) * HW + hh) * HW + ww;
        s_q[idx] = __bfloat162float(qkvb[(size_t)grow * (3 * DH) + c]) * scale;
    }

    // ---- neighbor-row table ----
    for (int idx = tid; idx < 16 * KCUBE; idx += 256) {
        const int i = idx / KCUBE, nb = idx - i * KCUBE;
        const int kt = nb / 9, kh = (nb / 3) % 3, kw = nb % 3;
        const int hh = h0 + (i >> 2), ww = w0 + (i & 3);
        const int sh = min(max(hh - 1, 0), HW - 3);
        const int sw = min(max(ww - 1, 0), HW - 3);
        s_r[idx] = (kt * nH + (sh + kh - hU0)) * nW + (sw + kw - wU0);
    }
    __syncthreads();

    // ---- scores + bias ----
    for (int idx = tid; idx < 16 * 108; idx += 256) {
        const int i   = idx / 108;
        const int rem = idx - i * 108;
        const int head = rem / KCUBE, nb = rem - head * KCUBE;
        const int r = s_r[i * KCUBE + nb];
        const __nv_bfloat16* kp = s_k + r * KSTR + head * HDIM;
        const float* qp = s_q + i * DH + head * HDIM;
        float s = 0.f;
        #pragma unroll
        for (int j = 0; j < HDIM; j++)
            s = fmaf(qp[j], __bfloat162float(kp[j]), s);
        const int kt = nb / 9, kh = (nb / 3) % 3, kw = nb % 3;
        const int hh = h0 + (i >> 2), ww = w0 + (i & 3);
        const int sh = min(max(hh - 1, 0), HW - 3);
        const int sw = min(max(ww - 1, 0), HW - 3);
        const int rt = st + kt - t + 2;
        const int rh = sh + kh - hh + 2;
        const int rw = sw + kw - ww + 2;
        s += rpb[((head * 5 + rt) * 5 + rh) * 5 + rw];
        s_p[idx] = s;
    }
    __syncthreads();

    // ---- softmax: 64 parallel (token, head) rows ----
    if (tid < 64) {
        const int i = tid >> 2, head = tid & 3;
        float* pp = s_p + i * 108 + head * KCUBE;
        float mx = -1e30f;
        #pragma unroll
        for (int k = 0; k < KCUBE; k++) mx = fmaxf(mx, pp[k]);
        float sum = 0.f;
        #pragma unroll
        for (int k = 0; k < KCUBE; k++) { float e = __expf(pp[k] - mx); pp[k] = e; sum += e; }
        const float inv = 1.0f / sum;
        #pragma unroll
        for (int k = 0; k < KCUBE; k++) pp[k] *= inv;
    }
    __syncthreads();

    // ---- output: o = P @ V ----
    for (int idx = tid; idx < 16 * DH; idx += 256) {
        const int i = idx / DH, c = idx - i * DH;
        const int head = c / HDIM;
        const float* pp = s_p + i * 108 + head * KCUBE;
        const int*   rt = s_r + i * KCUBE;
        float o = 0.f;
        #pragma unroll
        for (int nb = 0; nb < KCUBE; nb++)
            o = fmaf(pp[nb], __bfloat162float(s_v[rt[nb] * KSTR + c]), o);
        const int hh = h0 + (i >> 2), ww = w0 + (i & 3);
        const int grow = ((b * T_FR + t) * HW + hh) * HW + ww;
        att[(size_t)grow * DH + c] = __float2bfloat16(o);
    }
}

// ---------------- launch ----------------
extern "C" void kernel_launch(void* const* d_in, const int* in_sizes, int n_in,
                              void* d_out, int out_size)
{
    const float* x       = (const float*)d_in[0];
    const float* fc1_w   = (const float*)d_in[1];
    const float* fc1_b   = (const float*)d_in[2];
    const float* convA_w = (const float*)d_in[3];
    const float* convA_b = (const float*)d_in[4];
    const float* convB_w = (const float*)d_in[5];
    const float* convB_b = (const float*)d_in[6];
    const float* ln_g    = (const float*)d_in[7];
    const float* ln_b    = (const float*)d_in[8];
    const float* qkv_w   = (const float*)d_in[9];
    const float* qkv_b   = (const float*)d_in[10];
    const float* rpb     = (const float*)d_in[11];
    const float* proj_w  = (const float*)d_in[12];
    const float* proj_b  = (const float*)d_in[13];
    const float* fc2_w   = (const float*)d_in[14];
    const float* fc2_b   = (const float*)d_in[15];
    float* out = (float*)d_out;

    float *t1, *xs, *bconv;
    __nv_bfloat16 *xb, *t1b, *xsb, *yb, *qkvb, *attb;
    __nv_bfloat16 *wfc1, *wconv, *wqkv, *wproj, *wfc2;
    cudaGetSymbolAddress((void**)&t1,    g_t1);
    cudaGetSymbolAddress((void**)&xs,    g_xs);
    cudaGetSymbolAddress((void**)&bconv, g_b_conv);
    cudaGetSymbolAddress((void**)&xb,    g_xb);
    cudaGetSymbolAddress((void**)&t1b,   g_t1b);
    cudaGetSymbolAddress((void**)&xsb,   g_xsb);
    cudaGetSymbolAddress((void**)&yb,    g_yb);
    cudaGetSymbolAddress((void**)&qkvb,  g_qkvb);
    cudaGetSymbolAddress((void**)&attb,  g_attb);
    cudaGetSymbolAddress((void**)&wfc1,  g_w_fc1);
    cudaGetSymbolAddress((void**)&wconv, g_w_conv);
    cudaGetSymbolAddress((void**)&wqkv,  g_w_qkv);
    cudaGetSymbolAddress((void**)&wproj, g_w_proj);
    cudaGetSymbolAddress((void**)&wfc2,  g_w_fc2);

    cudaFuncSetAttribute(attn_tiled,
                         cudaFuncAttributeMaxDynamicSharedMemorySize, SMEM_ATT);

    const int gyA = (M_ALL + 127) / 128;   // 129
    const int gyP = M_PAT / 128;           // 128

    // 0) conversions + conv-weight fold
    {
        const int n = M_ALL * D_MOD;
        f2b_kernel<<<(n / 4 + 255) / 256, 256>>>(x, xb, n);
        wconv_kernel<<<114, 256>>>(fc1_w, qkv_w, proj_w, fc2_w);
        mconv_kernel<<<(DH * DH + DH + 255) / 256, 256>>>(convA_w, convA_b,
                                                          convB_w, convB_b);
    }
    // 1) fc1 -> t1 (f32) + t1b (bf16)
    tc_gemm<0, true, true><<<dim3(3, gyA), 256>>>(xb, wfc1, fc1_b, t1, t1b,
                                                  M_ALL, DH, D_MOD, nullptr);
    // 2) fused conv: gelu(t1 + t1b@Mc^T + b') -> xs (f32) + xsb (bf16)
    tc_gemm<1, true, true><<<dim3(3, gyA), 256>>>(t1b, wconv, bconv, xs, xsb,
                                                  M_ALL, DH, DH, t1);
    // 3) LayerNorm -> yb (bf16)
    ln_warp<<<M_PAT / 8, 256>>>(xs, ln_g, ln_b, yb);
    // 4) qkv -> qkvb (bf16 only)
    tc_gemm<0, false, true><<<dim3(9, gyP), 256>>>(yb, wqkv, qkv_b, nullptr, qkvb,
                                                   M_PAT, 3 * DH, DH, nullptr);
    // 5) tiled attention -> attb (bf16)
    attn_tiled<<<BATCH * T_FR * 16, 256, SMEM_ATT>>>(qkvb, rpb, attb);
    // 6) proj: xsb[rr] = xs[rr] + proj(attb) + b   (bf16 out only)
    tc_gemm<2, false, true><<<dim3(3, gyP), 256>>>(attb, wproj, proj_b, nullptr, xsb,
                                                   M_PAT, DH, DH, xs);
    // 7) fc2 + outer residual(x) -> out (f32)
    tc_gemm<3, true, false><<<dim3(12, gyA), 256>>>(xsb, wfc2, fc2_b, out, nullptr,
                                                    M_ALL, D_MOD, DH, x);
}